// round 9
// baseline (speedup 1.0000x reference)
#include <cuda_runtime.h>
#include <cuda_fp16.h>
#include <math.h>

// Problem dims (fixed by dataset)
#define MAXN 50000
#define MAXE 850000   // 800000 edges + 50000 self loops
#define IN_DIM 256
#define H1DIM 128     // 8 heads * 16
#define HEADS1 8
#define H2DIM 64
#define NEG_SLOPE 0.2f

// ---------------- scratch (static device globals; no allocation) -------------
__device__ __half g_h1h[MAXN * H1DIM];    // fp16 h1 (agg1 gather)
__device__ float  g_s1src[MAXN * HEADS1];
__device__ float  g_s1dst[MAXN * HEADS1];
__device__ int    g_deg[MAXN];
__device__ int    g_rowptr[MAXN + 1];
__device__ int    g_cursor[MAXN];
__device__ int    g_esrc[MAXE];
__device__ float  g_out1[MAXN * H1DIM];
__device__ __half g_h2h[MAXN * H2DIM];    // fp16 h2 (agg2 gather)
__device__ float  g_s2src[MAXN];
__device__ float  g_s2dst[MAXN];
__device__ int    g_is64;

// ---------------- helpers -----------------------------------------------------
__device__ __forceinline__ int edge_at(const void* ei, size_t idx) {
    if (g_is64) return (int)((const long long*)ei)[idx];
    return ((const int*)ei)[idx];
}

__device__ __forceinline__ float to_tf32(float x) {
    float r;
    asm("cvt.rna.tf32.f32 %0, %1;" : "=f"(r) : "f"(x));
    return r;
}

__device__ __forceinline__ float lrelu(float v) {
    return (v > 0.f) ? v : NEG_SLOPE * v;
}

__device__ __forceinline__ void mma_tf32(float* d, const unsigned* a,
                                         unsigned b0, unsigned b1) {
    asm volatile(
        "mma.sync.aligned.m16n8k8.row.col.f32.tf32.tf32.f32 "
        "{%0,%1,%2,%3}, {%4,%5,%6,%7}, {%8,%9}, {%0,%1,%2,%3};"
        : "+f"(d[0]), "+f"(d[1]), "+f"(d[2]), "+f"(d[3])
        : "r"(a[0]), "r"(a[1]), "r"(a[2]), "r"(a[3]), "r"(b0), "r"(b1));
}

// ---------------- init: deg=1 everywhere + edge-dtype detect ------------------
__global__ void init_kernel(const int* __restrict__ ei32, int Nn) {
    int i = blockIdx.x * blockDim.x + threadIdx.x;
    if (i < Nn) g_deg[i] = 1;   // self loop pre-counted
    if (i == 0) {
        int all_zero = 1;
        for (int k = 0; k < 64; k++)
            if (ei32[2 * k + 1] != 0) { all_zero = 0; break; }
        g_is64 = all_zero;
    }
}

// ---------------- tf32 GEMM body with fused score epilogue --------------------
// WHICH==0: A=arg(x), out=g_h1h + s1src/s1dst (per-head dots).
// WHICH==1: A=g_out1,  out=g_h2h + s2src/s2dst (full-row dots).
// fp32 product matrix is never materialized.
template <int BN, int WHICH>
__device__ __forceinline__ void gemm_body(const float* __restrict__ Aarg,
                                          const float* __restrict__ B,
                                          const float* __restrict__ sc_s,
                                          const float* __restrict__ sc_d,
                                          int M, int K, int bidx) {
    const float* __restrict__ A = (WHICH == 0) ? Aarg : (const float*)g_out1;
    __half* __restrict__ Ch = (WHICH == 0) ? g_h1h : g_h2h;

    constexpr int KB   = 32;
    constexpr int NW_N = BN / 64;
    constexpr int WM   = 128 / (8 / NW_N);
    constexpr int MAT  = WM / 16;
    constexpr int NAT  = 8;

    __shared__ float As[128][36];
    __shared__ float Bs[KB][BN + 4];

    const int tid  = threadIdx.x;
    const int wid  = tid >> 5;
    const int lane = tid & 31;
    const int wm   = (wid / NW_N) * WM;
    const int wn   = (wid % NW_N) * 64;
    const int bm   = bidx * 128;
    const int lq   = lane & 3;
    const int lg   = lane >> 2;

    float acc[MAT][NAT][4];
#pragma unroll
    for (int i = 0; i < MAT; i++)
#pragma unroll
        for (int j = 0; j < NAT; j++)
#pragma unroll
            for (int c = 0; c < 4; c++) acc[i][j][c] = 0.0f;

    for (int k0 = 0; k0 < K; k0 += KB) {
#pragma unroll
        for (int i = 0; i < 4; i++) {
            int idx = tid + i * 256;
            int row = idx >> 3;
            int kc  = (idx & 7) * 4;
            int gm  = bm + row;
            int gmc = (gm < M) ? gm : (M - 1);
            float4 v = *(const float4*)(A + (size_t)gmc * K + k0 + kc);
            if (gm >= M) v = make_float4(0.f, 0.f, 0.f, 0.f);
            v.x = to_tf32(v.x); v.y = to_tf32(v.y);
            v.z = to_tf32(v.z); v.w = to_tf32(v.w);
            *(float4*)&As[row][kc] = v;
        }
#pragma unroll
        for (int i = 0; i < (KB * BN) / (4 * 256); i++) {
            int idx = tid + i * 256;
            int kk  = idx / (BN / 4);
            int nc  = (idx % (BN / 4)) * 4;
            float4 v = *(const float4*)(B + (size_t)(k0 + kk) * BN + nc);
            v.x = to_tf32(v.x); v.y = to_tf32(v.y);
            v.z = to_tf32(v.z); v.w = to_tf32(v.w);
            *(float4*)&Bs[kk][nc] = v;
        }
        __syncthreads();
#pragma unroll
        for (int ks = 0; ks < KB; ks += 8) {
            unsigned a[MAT][4];
#pragma unroll
            for (int i = 0; i < MAT; i++) {
                int m0 = wm + i * 16;
                a[i][0] = __float_as_uint(As[m0 + lg][ks + lq]);
                a[i][1] = __float_as_uint(As[m0 + lg + 8][ks + lq]);
                a[i][2] = __float_as_uint(As[m0 + lg][ks + lq + 4]);
                a[i][3] = __float_as_uint(As[m0 + lg + 8][ks + lq + 4]);
            }
#pragma unroll
            for (int j = 0; j < NAT; j++) {
                unsigned b0 = __float_as_uint(Bs[ks + lq][wn + j * 8 + lg]);
                unsigned b1 = __float_as_uint(Bs[ks + lq + 4][wn + j * 8 + lg]);
#pragma unroll
                for (int i = 0; i < MAT; i++) mma_tf32(acc[i][j], a[i], b0, b1);
            }
        }
        __syncthreads();
    }

    // ---- epilogue: fp16 store + fused score dots -----------------------------
#pragma unroll
    for (int i = 0; i < MAT; i++) {
        int r0 = bm + wm + i * 16 + lg;
        int r1 = r0 + 8;
#pragma unroll
        for (int j = 0; j < NAT; j++) {
            int n0 = wn + j * 8 + 2 * lq;
            if (r0 < M)
                *(__half2*)(Ch + (size_t)r0 * BN + n0) =
                    __floats2half2_rn(acc[i][j][0], acc[i][j][1]);
            if (r1 < M)
                *(__half2*)(Ch + (size_t)r1 * BN + n0) =
                    __floats2half2_rn(acc[i][j][2], acc[i][j][3]);
        }
        if (WHICH == 0) {
            // per-head (16-col) dots; this warp owns heads wn/16 .. wn/16+3
#pragma unroll
            for (int hl = 0; hl < 4; hl++) {
                int head = (wn >> 4) + hl;
                float ss0 = 0.f, sd0 = 0.f, ss1 = 0.f, sd1 = 0.f;
#pragma unroll
                for (int jj = 0; jj < 2; jj++) {
                    int jidx = 2 * hl + jj;
#pragma unroll
                    for (int c = 0; c < 2; c++) {
                        float cs = __ldg(&sc_s[head * 16 + jj * 8 + 2 * lq + c]);
                        float cd = __ldg(&sc_d[head * 16 + jj * 8 + 2 * lq + c]);
                        ss0 = fmaf(acc[i][jidx][c], cs, ss0);
                        sd0 = fmaf(acc[i][jidx][c], cd, sd0);
                        ss1 = fmaf(acc[i][jidx][c + 2], cs, ss1);
                        sd1 = fmaf(acc[i][jidx][c + 2], cd, sd1);
                    }
                }
                ss0 += __shfl_xor_sync(0xFFFFFFFFu, ss0, 1);
                ss0 += __shfl_xor_sync(0xFFFFFFFFu, ss0, 2);
                sd0 += __shfl_xor_sync(0xFFFFFFFFu, sd0, 1);
                sd0 += __shfl_xor_sync(0xFFFFFFFFu, sd0, 2);
                ss1 += __shfl_xor_sync(0xFFFFFFFFu, ss1, 1);
                ss1 += __shfl_xor_sync(0xFFFFFFFFu, ss1, 2);
                sd1 += __shfl_xor_sync(0xFFFFFFFFu, sd1, 1);
                sd1 += __shfl_xor_sync(0xFFFFFFFFu, sd1, 2);
                if (lq == 0) {
                    if (r0 < M) {
                        g_s1src[(size_t)r0 * HEADS1 + head] = ss0;
                        g_s1dst[(size_t)r0 * HEADS1 + head] = sd0;
                    }
                    if (r1 < M) {
                        g_s1src[(size_t)r1 * HEADS1 + head] = ss1;
                        g_s1dst[(size_t)r1 * HEADS1 + head] = sd1;
                    }
                }
            }
        } else {
            // full-row (64-col) dots
            float ss0 = 0.f, sd0 = 0.f, ss1 = 0.f, sd1 = 0.f;
#pragma unroll
            for (int j = 0; j < NAT; j++) {
#pragma unroll
                for (int c = 0; c < 2; c++) {
                    float cs = __ldg(&sc_s[j * 8 + 2 * lq + c]);
                    float cd = __ldg(&sc_d[j * 8 + 2 * lq + c]);
                    ss0 = fmaf(acc[i][j][c], cs, ss0);
                    sd0 = fmaf(acc[i][j][c], cd, sd0);
                    ss1 = fmaf(acc[i][j][c + 2], cs, ss1);
                    sd1 = fmaf(acc[i][j][c + 2], cd, sd1);
                }
            }
            ss0 += __shfl_xor_sync(0xFFFFFFFFu, ss0, 1);
            ss0 += __shfl_xor_sync(0xFFFFFFFFu, ss0, 2);
            sd0 += __shfl_xor_sync(0xFFFFFFFFu, sd0, 1);
            sd0 += __shfl_xor_sync(0xFFFFFFFFu, sd0, 2);
            ss1 += __shfl_xor_sync(0xFFFFFFFFu, ss1, 1);
            ss1 += __shfl_xor_sync(0xFFFFFFFFu, ss1, 2);
            sd1 += __shfl_xor_sync(0xFFFFFFFFu, sd1, 1);
            sd1 += __shfl_xor_sync(0xFFFFFFFFu, sd1, 2);
            if (lq == 0) {
                if (r0 < M) { g_s2src[r0] = ss0; g_s2dst[r0] = sd0; }
                if (r1 < M) { g_s2src[r1] = ss1; g_s2dst[r1] = sd1; }
            }
        }
    }
}

// ---------------- K1: gemm1(+scores1) blocks || histo blocks ------------------
__global__ __launch_bounds__(256)
void k1_gemm1_histo(const float* __restrict__ x, const float* __restrict__ W1,
                    const float* __restrict__ a1s, const float* __restrict__ a1d,
                    const void* __restrict__ ei, int M, int E, int nGemmBlocks) {
    if ((int)blockIdx.x < nGemmBlocks) {
        gemm_body<H1DIM, 0>(x, W1, a1s, a1d, M, IN_DIM, blockIdx.x);
    } else {
        int e = (blockIdx.x - nGemmBlocks) * 256 + threadIdx.x;
        if (e < E) atomicAdd(&g_deg[edge_at(ei, (size_t)E + e)], 1);
    }
}

// ---------------- scan (1 block) ----------------------------------------------
__global__ __launch_bounds__(1024)
void scan_kernel(int Nn) {
    __shared__ int sums[2048];
    int tid = threadIdx.x;
    int chunk = (Nn + 1023) >> 10;
    int b = tid * chunk;
    int e = min(b + chunk, Nn);
    int s = 0;
    for (int i = b; i < e; i++) s += g_deg[i];
    sums[tid] = 0;
    sums[1024 + tid] = s;
    __syncthreads();
    for (int off = 1; off < 1024; off <<= 1) {
        int v = sums[1024 + tid - off];
        __syncthreads();
        sums[1024 + tid] += v;
        __syncthreads();
    }
    int run = sums[1023 + tid];
    for (int i = b; i < e; i++) {
        g_rowptr[i] = run;
        g_cursor[i] = run;
        run += g_deg[i];
    }
    if (tid == 1023) g_rowptr[Nn] = sums[2047];
}

// ---------------- scatter edges to CSR -----------------------------------------
__global__ __launch_bounds__(256)
void scatter_kernel(const void* __restrict__ ei, int E, int Nn) {
    int idx = blockIdx.x * blockDim.x + threadIdx.x;
    if (idx >= E + Nn) return;
    int src, dst;
    if (idx < E) {
        src = edge_at(ei, (size_t)idx);
        dst = edge_at(ei, (size_t)E + idx);
    } else {
        src = dst = idx - E;  // self loop
    }
    int pos = atomicAdd(&g_cursor[dst], 1);
    g_esrc[pos] = src;
}

// ---------------- layer-1 softmax+agg (fp16 gather, 8x unroll) ----------------
__global__ __launch_bounds__(256)
void agg1_kernel(const float* __restrict__ b1, int Nn) {
    int warp = (blockIdx.x * blockDim.x + threadIdx.x) >> 5;
    int lane = threadIdx.x & 31;
    if (warp >= Nn) return;
    int beg = g_rowptr[warp], end = g_rowptr[warp + 1];
    const int head = lane >> 2;
    const float sdst = g_s1dst[(size_t)warp * HEADS1 + head];

    float4 acc = make_float4(0.f, 0.f, 0.f, 0.f);
    float s = 0.f;
    int j = beg;
    for (; j + 7 < end; j += 8) {
        int   idx[8];
        float w[8];
        uint2 u[8];
#pragma unroll
        for (int t = 0; t < 8; t++) idx[t] = g_esrc[j + t];
#pragma unroll
        for (int t = 0; t < 8; t++)
            u[t] = *(const uint2*)(g_h1h + (size_t)idx[t] * H1DIM + lane * 4);
#pragma unroll
        for (int t = 0; t < 8; t++)
            w[t] = __expf(lrelu(g_s1src[(size_t)idx[t] * HEADS1 + head] + sdst));
#pragma unroll
        for (int t = 0; t < 8; t++) {
            s += w[t];
            float2 p = __half22float2(*(__half2*)&u[t].x);
            float2 q = __half22float2(*(__half2*)&u[t].y);
            acc.x = fmaf(w[t], p.x, acc.x); acc.y = fmaf(w[t], p.y, acc.y);
            acc.z = fmaf(w[t], q.x, acc.z); acc.w = fmaf(w[t], q.y, acc.w);
        }
    }
    for (; j < end; ++j) {
        int i0 = g_esrc[j];
        float w0 = __expf(lrelu(g_s1src[(size_t)i0 * HEADS1 + head] + sdst));
        uint2 u0 = *(const uint2*)(g_h1h + (size_t)i0 * H1DIM + lane * 4);
        s += w0;
        float2 p = __half22float2(*(__half2*)&u0.x);
        float2 q = __half22float2(*(__half2*)&u0.y);
        acc.x = fmaf(w0, p.x, acc.x); acc.y = fmaf(w0, p.y, acc.y);
        acc.z = fmaf(w0, q.x, acc.z); acc.w = fmaf(w0, q.y, acc.w);
    }
    float inv = 1.0f / s;
    float4 bb = *(const float4*)(b1 + lane * 4);
    float4 o;
    o.x = acc.x * inv + bb.x;  o.y = acc.y * inv + bb.y;
    o.z = acc.z * inv + bb.z;  o.w = acc.w * inv + bb.w;
    o.x = (o.x > 0.f) ? o.x : (__expf(o.x) - 1.0f);
    o.y = (o.y > 0.f) ? o.y : (__expf(o.y) - 1.0f);
    o.z = (o.z > 0.f) ? o.z : (__expf(o.z) - 1.0f);
    o.w = (o.w > 0.f) ? o.w : (__expf(o.w) - 1.0f);
    *(float4*)(g_out1 + (size_t)warp * H1DIM + lane * 4) = o;
}

// ---------------- gemm2 (+scores2 epilogue) ------------------------------------
__global__ __launch_bounds__(256)
void gemm2_kernel(const float* __restrict__ W2, const float* __restrict__ a2s,
                  const float* __restrict__ a2d, int M) {
    gemm_body<H2DIM, 1>(nullptr, W2, a2s, a2d, M, H1DIM, blockIdx.x);
}

// ---------------- layer-2 softmax+agg (fp16 gather, 8x) + log_softmax ---------
__global__ __launch_bounds__(256)
void agg2_kernel(const float* __restrict__ b2, float* __restrict__ dout, int Nn) {
    int warp = (blockIdx.x * blockDim.x + threadIdx.x) >> 5;
    int lane = threadIdx.x & 31;
    if (warp >= Nn) return;
    int beg = g_rowptr[warp], end = g_rowptr[warp + 1];
    const float sdst = g_s2dst[warp];

    float a0 = 0.f, a1 = 0.f, s = 0.f;
    int j = beg;
    for (; j + 7 < end; j += 8) {
        int     idx[8];
        float   w[8];
        __half2 u[8];
#pragma unroll
        for (int t = 0; t < 8; t++) idx[t] = g_esrc[j + t];
#pragma unroll
        for (int t = 0; t < 8; t++)
            u[t] = *(const __half2*)(g_h2h + (size_t)idx[t] * H2DIM + lane * 2);
#pragma unroll
        for (int t = 0; t < 8; t++)
            w[t] = __expf(lrelu(g_s2src[idx[t]] + sdst));
#pragma unroll
        for (int t = 0; t < 8; t++) {
            s += w[t];
            float2 f = __half22float2(u[t]);
            a0 = fmaf(w[t], f.x, a0); a1 = fmaf(w[t], f.y, a1);
        }
    }
    for (; j < end; ++j) {
        int i0 = g_esrc[j];
        float w0 = __expf(lrelu(g_s2src[i0] + sdst));
        __half2 u0 = *(const __half2*)(g_h2h + (size_t)i0 * H2DIM + lane * 2);
        s += w0;
        float2 f = __half22float2(u0);
        a0 = fmaf(w0, f.x, a0); a1 = fmaf(w0, f.y, a1);
    }
    float inv = 1.0f / s;
    float2 bb = *(const float2*)(b2 + lane * 2);
    float o0 = a0 * inv + bb.x;
    float o1 = a1 * inv + bb.y;

    float mx = fmaxf(o0, o1);
#pragma unroll
    for (int o = 16; o > 0; o >>= 1) mx = fmaxf(mx, __shfl_xor_sync(0xFFFFFFFFu, mx, o));
    float se = __expf(o0 - mx) + __expf(o1 - mx);
#pragma unroll
    for (int o = 16; o > 0; o >>= 1) se += __shfl_xor_sync(0xFFFFFFFFu, se, o);
    float lse = __logf(se);
    float2 r;  r.x = o0 - mx - lse;  r.y = o1 - mx - lse;
    *(float2*)(dout + (size_t)warp * H2DIM + lane * 2) = r;
}

// ---------------- launch (pure kernel launches, default stream) --------------
extern "C" void kernel_launch(void* const* d_in, const int* in_sizes, int n_in,
                              void* d_out, int out_size) {
    const float* x   = (const float*)d_in[0];
    const void*  ei  = d_in[1];
    const float* W1  = (const float*)d_in[2];
    const float* a1s = (const float*)d_in[3];
    const float* a1d = (const float*)d_in[4];
    const float* b1  = (const float*)d_in[5];
    const float* W2  = (const float*)d_in[6];
    const float* a2s = (const float*)d_in[7];
    const float* a2d = (const float*)d_in[8];
    const float* b2  = (const float*)d_in[9];
    float*       out = (float*)d_out;

    const int Nn   = in_sizes[0] / IN_DIM;  // 50000
    const int E    = in_sizes[1] / 2;       // 800000
    const int Etot = E + Nn;

    const int nG1 = (Nn + 127) / 128;   // gemm1 blocks
    const int nH  = (E + 255) / 256;    // histo blocks

    init_kernel<<<(Nn + 255) / 256, 256>>>((const int*)ei, Nn);
    k1_gemm1_histo<<<nG1 + nH, 256>>>(x, W1, a1s, a1d, ei, Nn, E, nG1);
    scan_kernel<<<1, 1024>>>(Nn);
    scatter_kernel<<<(Etot + 255) / 256, 256>>>(ei, E, Nn);
    agg1_kernel<<<(Nn + 7) / 8, 256>>>(b1, Nn);

    gemm2_kernel<<<(Nn + 127) / 128, 256>>>(W2, a2s, a2d, Nn);
    agg2_kernel<<<(Nn + 7) / 8, 256>>>(b2, out, Nn);
}